// round 11
// baseline (speedup 1.0000x reference)
#include <cuda_runtime.h>
#include <cuda_bf16.h>
#include <cstdint>

// ---------------- geometry ----------------
#define CIN   64
#define COUT  64
#define DD    16
#define HH    64
#define WW    64
#define POS   (DD*HH*WW)        // 65536
// padded k/v: [COUT][DP][HPD][WPD], interior at (+1,+1,+1)
#define DP    18
#define HPD   66
#define WPD   68
#define HS    (HPD*WPD)         // 4488
#define CS    (DP*HS)           // 80784

// Scratch: zero-initialized device globals. Pad rims of g_K/g_V are NEVER
// written, so they remain zero across all launches (deterministic).
__device__ __align__(16) float g_Q[COUT * POS];
__device__ __align__(16) float g_K[COUT * CS];
__device__ __align__(16) float g_V[COUT * CS];
// W in bf16 hi/lo split, [192 co][64 ci] (q:0-63, k:64-127, v:128-191)
__device__ __align__(16) unsigned short g_WH[192 * 64];
__device__ __align__(16) unsigned short g_WL[192 * 64];

__device__ __forceinline__ float ex2f(float s) {
    float e; asm("ex2.approx.ftz.f32 %0, %1;" : "=f"(e) : "f"(s)); return e;
}
__device__ __forceinline__ void mma16816(float* d, const unsigned* a,
                                         unsigned b0, unsigned b1) {
    asm volatile(
        "mma.sync.aligned.m16n8k16.row.col.f32.bf16.bf16.f32 "
        "{%0,%1,%2,%3},{%4,%5,%6,%7},{%8,%9},{%0,%1,%2,%3};"
        : "+f"(d[0]), "+f"(d[1]), "+f"(d[2]), "+f"(d[3])
        : "r"(a[0]), "r"(a[1]), "r"(a[2]), "r"(a[3]), "r"(b0), "r"(b1));
}
__device__ __forceinline__ unsigned bf16_hi(float v) {
    return (unsigned)__bfloat16_as_ushort(__float2bfloat16(v));
}

// ---------------- kernel 0: W -> bf16 hi/lo split ----------------
__global__ void wprep_kernel(const float* __restrict__ wq,
                             const float* __restrict__ wk,
                             const float* __restrict__ wv)
{
    int e = blockIdx.x * 1024 + threadIdx.x;      // 0..12287
    float v = (e < 4096) ? wq[e] : (e < 8192) ? wk[e - 4096] : wv[e - 8192];
    unsigned hu = bf16_hi(v);
    float hif = __uint_as_float(hu << 16);
    g_WH[e] = (unsigned short)hu;
    g_WL[e] = (unsigned short)bf16_hi(v - hif);
}

// ---------------- kernel 1: projection via mma.sync bf16 triple-split ----
// C[192 co][128 pos tile] = W[192x64] @ X[64x128], fp32 accum,
// products Whi*Xhi + Whi*Xlo + Wlo*Xhi.
// Block 512 = 16 warps: warp w -> co-group (w>>2)*48, pos-quarter (w&3)*32.
// Warp tile 48co x 32pos -> 48 accum regs, ~90 total: no spills, 2+ CTAs/SM.
// B tiles: n-major bf16 rows, 144B stride (conflict-free fragment LDS).
#define STG_STRIDE 132                      // fp32 words per stage row
#define B_STRIDE   144                      // bytes per B row (64 bf16 + pad)
#define SM_STAGE_BYTES (64 * STG_STRIDE * 4)    // 33792
#define SM_BHI  SM_STAGE_BYTES
#define SM_BLO  (SM_BHI + 128 * B_STRIDE)       // +18432
#define SMEM_DYN (SM_BLO + 128 * B_STRIDE)      // 70656

__global__ __launch_bounds__(512) void proj_mma_kernel(const float* __restrict__ x)
{
    extern __shared__ __align__(16) char sm[];
    float* stage = (float*)sm;
    char*  Bhi   = sm + SM_BHI;
    char*  Blo   = sm + SM_BLO;

    const int t    = threadIdx.x;
    const int wid  = t >> 5;
    const int lane = t & 31;
    const int pos0 = blockIdx.x * 128;

    // ---- load x tile [64 ci][128 pos] into fp32 stage (coalesced) ----
    #pragma unroll
    for (int i = 0; i < 4; i++) {
        int idx4 = i * 512 + t;             // 0..2047 float4s
        int ci = idx4 >> 5, pq = idx4 & 31;
        float4 vx = *(const float4*)(x + (size_t)ci * POS + pos0 + pq * 4);
        *(float4*)(stage + ci * STG_STRIDE + pq * 4) = vx;
    }
    __syncthreads();

    // ---- transpose + bf16 hi/lo: build B tiles [pos][ci] ----
    {
        const int p = t & 127;
        const int quarter = t >> 7;         // ci quarter 0..3 (16 ci each)
        #pragma unroll
        for (int oc = 0; oc < 2; oc++) {
            int ci0 = quarter * 16 + oc * 8;
            unsigned hb[8], lb[8];
            #pragma unroll
            for (int j = 0; j < 8; j++) {
                float v = stage[(ci0 + j) * STG_STRIDE + p];
                unsigned hu = bf16_hi(v);
                hb[j] = hu;
                lb[j] = bf16_hi(v - __uint_as_float(hu << 16));
            }
            uint4 H = { hb[0] | (hb[1] << 16), hb[2] | (hb[3] << 16),
                        hb[4] | (hb[5] << 16), hb[6] | (hb[7] << 16) };
            uint4 L = { lb[0] | (lb[1] << 16), lb[2] | (lb[3] << 16),
                        lb[4] | (lb[5] << 16), lb[6] | (lb[7] << 16) };
            *(uint4*)(Bhi + p * B_STRIDE + ci0 * 2) = H;
            *(uint4*)(Blo + p * B_STRIDE + ci0 * 2) = L;
        }
    }
    __syncthreads();

    // ---- MMA: warp tile 48 co x 32 pos, K=64 in 4 steps, 3 products ----
    const int cg  = wid >> 2;
    const int pq  = wid & 3;
    const int co0 = cg * 48;
    const int nb  = pq * 32;
    const int r   = lane >> 2;
    const int qd  = lane & 3;

    float d[3][4][4];
    #pragma unroll
    for (int m = 0; m < 3; m++)
        #pragma unroll
        for (int n = 0; n < 4; n++)
            #pragma unroll
            for (int i = 0; i < 4; i++) d[m][n][i] = 0.f;

    const char* WHb = (const char*)g_WH;
    const char* WLb = (const char*)g_WL;

    #pragma unroll
    for (int k = 0; k < 4; k++) {
        #pragma unroll
        for (int m = 0; m < 3; m++) {
            unsigned AH[4], AL[4];
            int byte0 = (co0 + m * 16 + r) * 128 + k * 32 + qd * 4;
            AH[0] = *(const unsigned*)(WHb + byte0);
            AH[1] = *(const unsigned*)(WHb + byte0 + 8 * 128);
            AH[2] = *(const unsigned*)(WHb + byte0 + 16);
            AH[3] = *(const unsigned*)(WHb + byte0 + 8 * 128 + 16);
            AL[0] = *(const unsigned*)(WLb + byte0);
            AL[1] = *(const unsigned*)(WLb + byte0 + 8 * 128);
            AL[2] = *(const unsigned*)(WLb + byte0 + 16);
            AL[3] = *(const unsigned*)(WLb + byte0 + 8 * 128 + 16);
            #pragma unroll
            for (int n = 0; n < 4; n++) {
                int boff = (nb + n * 8 + r) * B_STRIDE + k * 32 + qd * 4;
                unsigned bh0 = *(const unsigned*)(Bhi + boff);
                unsigned bh1 = *(const unsigned*)(Bhi + boff + 16);
                unsigned bl0 = *(const unsigned*)(Blo + boff);
                unsigned bl1 = *(const unsigned*)(Blo + boff + 16);
                mma16816(d[m][n], AH, bh0, bh1);
                mma16816(d[m][n], AH, bl0, bl1);
                mma16816(d[m][n], AL, bh0, bh1);
            }
        }
    }

    // ---- epilogue: scatter to Q (dense) / K,V (padded) ----
    #pragma unroll
    for (int n = 0; n < 4; n++) {
        int pos = pos0 + nb + n * 8 + qd * 2;
        int dz = pos >> 12, hy = (pos >> 6) & 63, wx = pos & 63;
        size_t kvoff = (size_t)(dz + 1) * HS + (size_t)(hy + 1) * WPD + (wx + 1);
        #pragma unroll
        for (int m = 0; m < 3; m++) {
            #pragma unroll
            for (int half = 0; half < 2; half++) {
                int co = co0 + m * 16 + r + half * 8;
                float x0 = d[m][n][half * 2], x1 = d[m][n][half * 2 + 1];
                if (co < 64) {
                    float2 o = {x0, x1};
                    *(float2*)(g_Q + (size_t)co * POS + pos) = o;
                } else if (co < 128) {
                    float* dst = g_K + (size_t)(co - 64) * CS + kvoff;
                    dst[0] = x0; dst[1] = x1;
                } else {
                    float* dst = g_V + (size_t)(co - 128) * CS + kvoff;
                    dst[0] = x0; dst[1] = x1;
                }
            }
        }
    }
}

// ---------------- kernel 2: windowed softmax-attention ----------
// Grid: (h-tiles=8, d=16, c=64); block 128 = 8 h x 16 w-quads.
// rel bias varies along exactly one axis per channel -> 3 distinct values;
// premultiplied by qs so each tap is a single FFMA before ex2.
// Padded taps naturally give score q*rel (k=0 in rim) with v=0.
template<int AXIS>
__device__ __forceinline__ void attn_body(
    const float* __restrict__ relv, int c, int d, int h, int w0,
    float* __restrict__ out)
{
    const float LOG2E = 1.4426950408889634f;
    float4 q4 = *(const float4*)(g_Q + (size_t)c * POS + d * (HH * WW) + h * WW + w0);
    float qs[4] = {q4.x * LOG2E, q4.y * LOG2E, q4.z * LOG2E, q4.w * LOG2E};

    float rv0 = relv[0], rv1 = relv[1], rv2 = relv[2];
    float rq[4][3];
    #pragma unroll
    for (int i = 0; i < 4; i++) {
        rq[i][0] = qs[i] * rv0;
        rq[i][1] = qs[i] * rv1;
        rq[i][2] = qs[i] * rv2;
    }

    float l[4]   = {0.f, 0.f, 0.f, 0.f};
    float acc[4] = {0.f, 0.f, 0.f, 0.f};

    const float* kc = g_K + (size_t)c * CS + (size_t)d * HS + (size_t)h * WPD + w0;
    const float* vc = g_V + (size_t)c * CS + (size_t)d * HS + (size_t)h * WPD + w0;

    #pragma unroll
    for (int kd = 0; kd < 3; kd++) {
        #pragma unroll
        for (int kh = 0; kh < 3; kh++) {
            const float* kp = kc + kd * HS + kh * WPD;
            const float* vp = vc + kd * HS + kh * WPD;
            float4 ka = *(const float4*)kp;
            float2 kb = *(const float2*)(kp + 4);
            float4 va = *(const float4*)vp;
            float2 vb = *(const float2*)(vp + 4);
            float kk[6] = {ka.x, ka.y, ka.z, ka.w, kb.x, kb.y};
            float vv[6] = {va.x, va.y, va.z, va.w, vb.x, vb.y};
            #pragma unroll
            for (int kw = 0; kw < 3; kw++) {
                const int ax = (AXIS == 0) ? kd : (AXIS == 1) ? kh : kw;
                #pragma unroll
                for (int i = 0; i < 4; i++) {
                    float s = fmaf(kk[i + kw], qs[i], rq[i][ax]);
                    float e = ex2f(s);
                    l[i] += e;
                    acc[i] = fmaf(e, vv[i + kw], acc[i]);
                }
            }
        }
    }

    float4 o;
    o.x = __fdividef(acc[0], l[0]);
    o.y = __fdividef(acc[1], l[1]);
    o.z = __fdividef(acc[2], l[2]);
    o.w = __fdividef(acc[3], l[3]);
    *(float4*)(out + (size_t)c * POS + d * (HH * WW) + h * WW + w0) = o;
}

__global__ __launch_bounds__(128) void attn_kernel(
    const float* __restrict__ rel_d,
    const float* __restrict__ rel_h,
    const float* __restrict__ rel_w,
    float* __restrict__ out)
{
    const int c  = blockIdx.z;
    const int d  = blockIdx.y;
    const int t  = threadIdx.x;
    const int h  = blockIdx.x * 8 + (t >> 4);
    const int w0 = (t & 15) * 4;

    if (c < 21)      attn_body<0>(rel_d + c * 3, c, d, h, w0, out);
    else if (c < 42) attn_body<1>(rel_h + (c - 21) * 3, c, d, h, w0, out);
    else             attn_body<2>(rel_w + (c - 42) * 3, c, d, h, w0, out);
}

// ---------------- launch ----------------
extern "C" void kernel_launch(void* const* d_in, const int* in_sizes, int n_in,
                              void* d_out, int out_size)
{
    const float* x  = (const float*)d_in[0];
    const float* wq = (const float*)d_in[1];
    const float* wk = (const float*)d_in[2];
    const float* wv = (const float*)d_in[3];
    const float* rd = (const float*)d_in[4];
    const float* rh = (const float*)d_in[5];
    const float* rw = (const float*)d_in[6];
    float* out = (float*)d_out;

    cudaFuncSetAttribute(proj_mma_kernel,
                         cudaFuncAttributeMaxDynamicSharedMemorySize, SMEM_DYN);

    wprep_kernel<<<12, 1024>>>(wq, wk, wv);
    proj_mma_kernel<<<POS / 128, 512, SMEM_DYN>>>(x);

    dim3 g2(HH / 8, DD, COUT);
    attn_kernel<<<g2, 128>>>(rd, rh, rw, out);
}

// round 12
// speedup vs baseline: 1.7695x; 1.7695x over previous
#include <cuda_runtime.h>
#include <cuda_bf16.h>
#include <cstdint>

// ---------------- geometry ----------------
#define CIN   64
#define COUT  64
#define DD    16
#define HH    64
#define WW    64
#define POS   (DD*HH*WW)        // 65536
// padded k/v: [COUT][DP][HPD][WPD], interior at (+1,+1,+1)
#define DP    18
#define HPD   66
#define WPD   68
#define HS    (HPD*WPD)         // 4488
#define CS    (DP*HS)           // 80784

// Scratch: zero-initialized device globals. Pad rims of g_K/g_V are NEVER
// written, so they remain zero across all launches (deterministic).
__device__ __align__(16) float g_Q[COUT * POS];
__device__ __align__(16) float g_K[COUT * CS];
__device__ __align__(16) float g_V[COUT * CS];
// W in bf16 hi/lo split, [192 co][64 ci] (q:0-63, k:64-127, v:128-191)
__device__ __align__(16) unsigned short g_WH[192 * 64];
__device__ __align__(16) unsigned short g_WL[192 * 64];

__device__ __forceinline__ float ex2f(float s) {
    float e; asm("ex2.approx.ftz.f32 %0, %1;" : "=f"(e) : "f"(s)); return e;
}
__device__ __forceinline__ void mma16816(float* d, const unsigned* a,
                                         unsigned b0, unsigned b1) {
    asm volatile(
        "mma.sync.aligned.m16n8k16.row.col.f32.bf16.bf16.f32 "
        "{%0,%1,%2,%3},{%4,%5,%6,%7},{%8,%9},{%0,%1,%2,%3};"
        : "+f"(d[0]), "+f"(d[1]), "+f"(d[2]), "+f"(d[3])
        : "r"(a[0]), "r"(a[1]), "r"(a[2]), "r"(a[3]), "r"(b0), "r"(b1));
}
__device__ __forceinline__ unsigned bf16_hi(float v) {
    return (unsigned)__bfloat16_as_ushort(__float2bfloat16(v));
}

// ---------------- kernel 0: W -> bf16 hi/lo split ----------------
__global__ void wprep_kernel(const float* __restrict__ wq,
                             const float* __restrict__ wk,
                             const float* __restrict__ wv)
{
    int e = blockIdx.x * 1024 + threadIdx.x;      // 0..12287
    float v = (e < 4096) ? wq[e] : (e < 8192) ? wk[e - 4096] : wv[e - 8192];
    unsigned hu = bf16_hi(v);
    float hif = __uint_as_float(hu << 16);
    g_WH[e] = (unsigned short)hu;
    g_WL[e] = (unsigned short)bf16_hi(v - hif);
}

// ---------------- kernel 1: projection via mma.sync bf16 triple-split ----
// C[192 co][64 pos tile] = W[192x64] @ X[64x64], fp32 accum,
// products Whi*Xhi + Whi*Xlo + Wlo*Xhi.
// Block 128 = 4 warps, warp w -> co-group w*48, ALL warps share the 64 pos.
// Same 48co x 64pos warp tile / instruction mix as the 74.7us round-8 run,
// but 128-thread CTAs (~18K regs/CTA) -> 3 CTAs/SM instead of 1.
#define STG_STRIDE 68                       // fp32 words per stage row
#define B_STRIDE   144                      // bytes per B row (64 bf16 + pad)
#define SM_STAGE_BYTES (64 * STG_STRIDE * 4)    // 17408
#define SM_BHI  SM_STAGE_BYTES
#define SM_BLO  (SM_BHI + 64 * B_STRIDE)        // +9216
#define SMEM_DYN (SM_BLO + 64 * B_STRIDE)       // 35840

__global__ __launch_bounds__(128) void proj_mma_kernel(const float* __restrict__ x)
{
    extern __shared__ __align__(16) char sm[];
    float* stage = (float*)sm;
    char*  Bhi   = sm + SM_BHI;
    char*  Blo   = sm + SM_BLO;

    const int t    = threadIdx.x;
    const int wid  = t >> 5;
    const int lane = t & 31;
    const int pos0 = blockIdx.x * 64;

    // ---- load x tile [64 ci][64 pos] into fp32 stage (coalesced) ----
    #pragma unroll
    for (int i = 0; i < 8; i++) {
        int idx4 = i * 128 + t;             // 0..1023 float4s
        int ci = idx4 >> 4, pq = idx4 & 15;
        float4 vx = *(const float4*)(x + (size_t)ci * POS + pos0 + pq * 4);
        *(float4*)(stage + ci * STG_STRIDE + pq * 4) = vx;
    }
    __syncthreads();

    // ---- transpose + bf16 hi/lo: build B tiles [pos][ci] ----
    {
        const int p = t & 63;
        const int cihalf = t >> 6;          // ci half 0/1 (32 ci each)
        #pragma unroll
        for (int oc = 0; oc < 4; oc++) {
            int ci0 = cihalf * 32 + oc * 8;
            unsigned hb[8], lb[8];
            #pragma unroll
            for (int j = 0; j < 8; j++) {
                float v = stage[(ci0 + j) * STG_STRIDE + p];
                unsigned hu = bf16_hi(v);
                hb[j] = hu;
                lb[j] = bf16_hi(v - __uint_as_float(hu << 16));
            }
            uint4 H = { hb[0] | (hb[1] << 16), hb[2] | (hb[3] << 16),
                        hb[4] | (hb[5] << 16), hb[6] | (hb[7] << 16) };
            uint4 L = { lb[0] | (lb[1] << 16), lb[2] | (lb[3] << 16),
                        lb[4] | (lb[5] << 16), lb[6] | (lb[7] << 16) };
            *(uint4*)(Bhi + p * B_STRIDE + ci0 * 2) = H;
            *(uint4*)(Blo + p * B_STRIDE + ci0 * 2) = L;
        }
    }
    __syncthreads();

    // ---- MMA: warp tile 48 co x 64 pos, K=64 in 4 steps, 3 products ----
    const int co0 = wid * 48;
    const int r   = lane >> 2;
    const int qd  = lane & 3;

    float d[3][8][4];
    #pragma unroll
    for (int m = 0; m < 3; m++)
        #pragma unroll
        for (int n = 0; n < 8; n++)
            #pragma unroll
            for (int i = 0; i < 4; i++) d[m][n][i] = 0.f;

    const char* WHb = (const char*)g_WH;
    const char* WLb = (const char*)g_WL;

    #pragma unroll
    for (int k = 0; k < 4; k++) {
        unsigned AH[3][4], AL[3][4];
        #pragma unroll
        for (int m = 0; m < 3; m++) {
            int byte0 = (co0 + m * 16 + r) * 128 + k * 32 + qd * 4;
            AH[m][0] = *(const unsigned*)(WHb + byte0);
            AH[m][1] = *(const unsigned*)(WHb + byte0 + 8 * 128);
            AH[m][2] = *(const unsigned*)(WHb + byte0 + 16);
            AH[m][3] = *(const unsigned*)(WHb + byte0 + 8 * 128 + 16);
            AL[m][0] = *(const unsigned*)(WLb + byte0);
            AL[m][1] = *(const unsigned*)(WLb + byte0 + 8 * 128);
            AL[m][2] = *(const unsigned*)(WLb + byte0 + 16);
            AL[m][3] = *(const unsigned*)(WLb + byte0 + 8 * 128 + 16);
        }
        #pragma unroll
        for (int n = 0; n < 8; n++) {
            int boff = (n * 8 + r) * B_STRIDE + k * 32 + qd * 4;
            unsigned bh0 = *(const unsigned*)(Bhi + boff);
            unsigned bh1 = *(const unsigned*)(Bhi + boff + 16);
            unsigned bl0 = *(const unsigned*)(Blo + boff);
            unsigned bl1 = *(const unsigned*)(Blo + boff + 16);
            #pragma unroll
            for (int m = 0; m < 3; m++) {
                mma16816(d[m][n], AH[m], bh0, bh1);
                mma16816(d[m][n], AH[m], bl0, bl1);
                mma16816(d[m][n], AL[m], bh0, bh1);
            }
        }
    }

    // ---- epilogue: scatter to Q (dense) / K,V (padded) ----
    #pragma unroll
    for (int n = 0; n < 8; n++) {
        int pos = pos0 + n * 8 + qd * 2;
        int dz = pos >> 12, hy = (pos >> 6) & 63, wx = pos & 63;
        size_t kvoff = (size_t)(dz + 1) * HS + (size_t)(hy + 1) * WPD + (wx + 1);
        #pragma unroll
        for (int m = 0; m < 3; m++) {
            #pragma unroll
            for (int half = 0; half < 2; half++) {
                int co = co0 + m * 16 + r + half * 8;
                float x0 = d[m][n][half * 2], x1 = d[m][n][half * 2 + 1];
                if (co < 64) {
                    float2 o = {x0, x1};
                    *(float2*)(g_Q + (size_t)co * POS + pos) = o;
                } else if (co < 128) {
                    float* dst = g_K + (size_t)(co - 64) * CS + kvoff;
                    dst[0] = x0; dst[1] = x1;
                } else {
                    float* dst = g_V + (size_t)(co - 128) * CS + kvoff;
                    dst[0] = x0; dst[1] = x1;
                }
            }
        }
    }
}

// ---------------- kernel 2: windowed softmax-attention (scalar) ----------
// Grid: (h-tiles=8, d=16, c=64); block 128 = 8 h x 16 w-quads.
// Padded taps naturally give score q*rel (k=0 in rim) with v=0.
__global__ __launch_bounds__(128) void attn_kernel(
    const float* __restrict__ rel_d,
    const float* __restrict__ rel_h,
    const float* __restrict__ rel_w,
    float* __restrict__ out)
{
    __shared__ float srel[27];
    const int c  = blockIdx.z;
    const int d  = blockIdx.y;
    const int h0 = blockIdx.x * 8;
    const int t  = threadIdx.x;

    if (t < 27) {
        int kd = t / 9, kh = (t / 3) % 3, kw = t % 3;
        float r;
        if (c < 21)      r = rel_d[c * 3 + kd];
        else if (c < 42) r = rel_h[(c - 21) * 3 + kh];
        else             r = rel_w[(c - 42) * 3 + kw];
        srel[t] = r;
    }
    __syncthreads();

    const int ty = t >> 4;
    const int w0 = (t & 15) * 4;
    const int h  = h0 + ty;

    const float LOG2E = 1.4426950408889634f;
    float4 q4 = *(const float4*)(g_Q + (size_t)c * POS + d * (HH * WW) + h * WW + w0);
    float qs[4] = {q4.x * LOG2E, q4.y * LOG2E, q4.z * LOG2E, q4.w * LOG2E};

    float l[4]   = {0.f, 0.f, 0.f, 0.f};
    float acc[4] = {0.f, 0.f, 0.f, 0.f};

    const float* kc = g_K + (size_t)c * CS + (size_t)d * HS + (size_t)h * WPD + w0;
    const float* vc = g_V + (size_t)c * CS + (size_t)d * HS + (size_t)h * WPD + w0;

    #pragma unroll
    for (int kd = 0; kd < 3; kd++) {
        #pragma unroll
        for (int kh = 0; kh < 3; kh++) {
            const float* kp = kc + kd * HS + kh * WPD;
            const float* vp = vc + kd * HS + kh * WPD;
            float4 ka = *(const float4*)kp;
            float2 kb = *(const float2*)(kp + 4);
            float4 va = *(const float4*)vp;
            float2 vb = *(const float2*)(vp + 4);
            float kk[6] = {ka.x, ka.y, ka.z, ka.w, kb.x, kb.y};
            float vv[6] = {va.x, va.y, va.z, va.w, vb.x, vb.y};
            #pragma unroll
            for (int kw = 0; kw < 3; kw++) {
                float r = srel[(kd * 3 + kh) * 3 + kw];
                #pragma unroll
                for (int i = 0; i < 4; i++) {
                    float s = (kk[i + kw] + r) * qs[i];
                    float e = ex2f(s);
                    l[i] += e;
                    acc[i] = fmaf(e, vv[i + kw], acc[i]);
                }
            }
        }
    }

    float4 o;
    o.x = __fdividef(acc[0], l[0]);
    o.y = __fdividef(acc[1], l[1]);
    o.z = __fdividef(acc[2], l[2]);
    o.w = __fdividef(acc[3], l[3]);
    *(float4*)(out + (size_t)c * POS + d * (HH * WW) + h * WW + w0) = o;
}

// ---------------- launch ----------------
extern "C" void kernel_launch(void* const* d_in, const int* in_sizes, int n_in,
                              void* d_out, int out_size)
{
    const float* x  = (const float*)d_in[0];
    const float* wq = (const float*)d_in[1];
    const float* wk = (const float*)d_in[2];
    const float* wv = (const float*)d_in[3];
    const float* rd = (const float*)d_in[4];
    const float* rh = (const float*)d_in[5];
    const float* rw = (const float*)d_in[6];
    float* out = (float*)d_out;

    wprep_kernel<<<12, 1024>>>(wq, wk, wv);
    proj_mma_kernel<<<POS / 64, 128, SMEM_DYN>>>(x);

    dim3 g2(HH / 8, DD, COUT);
    attn_kernel<<<g2, 128>>>(rd, rh, rw, out);
}